// round 1
// baseline (speedup 1.0000x reference)
#include <cuda_runtime.h>
#include <math_constants.h>

// Problem constants (B=8, S=1024, V=32000)
#define BB 8
#define SS 1024
#define VV 32000
#define V4 (VV / 4)   // 8000 float4 per logits row

// Scratch: bonus position per batch row (device global — no allocation).
__device__ int g_bonus_pos[BB];

// Output layout (float32, tuple order):
//   [0 .. B*S)                      draft        (8192)
//   [B*S .. B*S+B)                  num_newly    (8)
//   [B*S+B .. B*S+2B)               num_acc      (8)
//   [B*S+2B .. B*S+2B+B*V)          last_logits  (256000)
#define OFF_NEWLY   (BB * SS)
#define OFF_ACC     (BB * SS + BB)
#define OFF_LOGITS  (BB * SS + 2 * BB)

// Kernel 1: per-row sequential verify. One block per batch row.
// Block-wide argmax over V=32000 per visited position; loop terminates at the
// first mismatch (expected after 1 iteration for random data) or at k == S-1.
__global__ __launch_bounds__(1024) void eagle_verify_kernel(
    const int*  __restrict__ input_ids,   // [B, S]
    const float* __restrict__ logits,     // [B, S, V]
    const int*  __restrict__ npa,         // [B]
    float* __restrict__ out)
{
    const int b   = blockIdx.x;
    const int tid = threadIdx.x;
    const int lane = tid & 31;
    const int warp = tid >> 5;

    __shared__ float s_val[32];
    __shared__ int   s_idx[32];
    __shared__ int   s_cont;     // 1 = continue scanning, 0 = stop
    __shared__ int   s_bonus;    // bonus token (written by thread 0 on stop)

    const int* ids = input_ids + b * SS;
    const int  start = npa[b] - 1;

    int k = start;
    int num_newly = 0;

    for (;;) {
        // ---- block argmax of logits[b, k, :] (first-occurrence tie-break) ----
        const float4* row =
            (const float4*)(logits + ((size_t)b * SS + (size_t)k) * VV);

        float best = -CUDART_INF_F;
        int   bidx = 0x7fffffff;
        #pragma unroll 2
        for (int i = tid; i < V4; i += 1024) {
            float4 v = row[i];
            int base = i * 4;
            // lanes scanned in increasing index, strict '>' keeps first max
            if (v.x > best) { best = v.x; bidx = base;     }
            if (v.y > best) { best = v.y; bidx = base + 1; }
            if (v.z > best) { best = v.z; bidx = base + 2; }
            if (v.w > best) { best = v.w; bidx = base + 3; }
        }
        // warp reduce (val desc, idx asc on ties)
        #pragma unroll
        for (int off = 16; off > 0; off >>= 1) {
            float ov = __shfl_down_sync(0xffffffffu, best, off);
            int   oi = __shfl_down_sync(0xffffffffu, bidx, off);
            if (ov > best || (ov == best && oi < bidx)) { best = ov; bidx = oi; }
        }
        if (lane == 0) { s_val[warp] = best; s_idx[warp] = bidx; }
        __syncthreads();

        if (warp == 0) {
            float v = s_val[lane];
            int   i = s_idx[lane];
            #pragma unroll
            for (int off = 16; off > 0; off >>= 1) {
                float ov = __shfl_down_sync(0xffffffffu, v, off);
                int   oi = __shfl_down_sync(0xffffffffu, i, off);
                if (ov > v || (ov == v && oi < i)) { v = ov; i = oi; }
            }
            if (lane == 0) {
                // greedy token at position k is i
                if (k < SS - 1 && i == ids[k + 1]) {
                    s_cont = 1;
                } else {
                    s_cont = 0;
                    s_bonus = i;
                }
            }
        }
        __syncthreads();

        if (!s_cont) break;
        ++k;
        ++num_newly;
    }

    // k == bonus_pos == start + num_newly ;  num_acc - 1 == k
    const int bonus_tok = s_bonus;

    if (tid == 0) {
        out[OFF_NEWLY + b] = (float)num_newly;
        out[OFF_ACC   + b] = (float)(start + 1 + num_newly);
        g_bonus_pos[b] = k;
    }

    // draft row: one element per thread (S == blockDim.x == 1024)
    int t = tid;
    int dv;
    if (t < k)        dv = ids[t + 1];
    else if (t == k)  dv = bonus_tok;
    else              dv = 0;
    out[b * SS + t] = (float)dv;
}

// Kernel 2: gather last_logits[b, :] = logits[b, bonus_pos[b], :]
// Spread over many SMs; float4 per thread.
__global__ __launch_bounds__(256) void eagle_gather_kernel(
    const float* __restrict__ logits,
    float* __restrict__ out)
{
    int i = blockIdx.x * blockDim.x + threadIdx.x;   // [0, B*V4)
    int b = i / V4;
    int r = i - b * V4;
    int pos = g_bonus_pos[b];
    const float4* src =
        (const float4*)(logits + ((size_t)b * SS + (size_t)pos) * VV);
    float4* dst = (float4*)(out + OFF_LOGITS) + (size_t)b * V4;
    dst[r] = src[r];
}

extern "C" void kernel_launch(void* const* d_in, const int* in_sizes, int n_in,
                              void* d_out, int out_size) {
    const int*   input_ids = (const int*)  d_in[0];
    const float* logits    = (const float*)d_in[1];
    const int*   npa       = (const int*)  d_in[2];
    float* out = (float*)d_out;

    eagle_verify_kernel<<<BB, 1024>>>(input_ids, logits, npa, out);
    // B*V/4 = 64000 float4 elements, 256 threads/block -> 250 blocks
    eagle_gather_kernel<<<(BB * V4) / 256, 256>>>(logits, out);
}